// round 12
// baseline (speedup 1.0000x reference)
#include <cuda_runtime.h>
#include <cstdint>

#define N_GT    128
#define NTX2    32          // 32x32 tiles of 32px
#define NTILES2 1024
#define MT      256
#define GRIDN   1024        // 1 anchor per thread
#define NPREP   4           // producer blocks (4*256 = 1 thread per tile)
#define CMAX    24          // per-tile candidate cap (mean ~4.7, tail ~16)
#define PAD     32          // 256B stride: spreads g_best across LTS slices

__device__ unsigned long long g_best[N_GT * PAD];   // zero-init; reset each run
__device__ unsigned           g_done  = 0;          // reset each run
__device__ unsigned           g_ready = 0;          // reset each run
__device__ int                g_cnt[NTILES2];
__device__ unsigned char      g_list[NTILES2 * CMAX];

__global__ __launch_bounds__(MT) void fused(
    const float4* __restrict__ anchor,
    const float4* __restrict__ gt,
    float* __restrict__ assign, int n)
{
    __shared__ unsigned long long s_best[N_GT];
    __shared__ int s_last;

    const int tid = threadIdx.x;
    const int b   = blockIdx.x;

    if (tid < N_GT) s_best[tid] = 0ull;

    if (b < NPREP) {
        // ---- Producers: gather per-tile GT candidate lists (once, no atomics).
        // Tile (tx,ty) takes gt iff an anchor with top-left corner in the tile
        // could overlap it: same conservative integer window as before.
        int t  = b * MT + tid;                 // tile id, exactly 1024 threads
        int tx = t & (NTX2 - 1), ty = t >> 5;
        int cnt = 0;
        for (int g = 0; g < N_GT; ++g) {
            float4 G = __ldg(&gt[g]);
            bool cov = (tx >= (((int)G.x - 97) >> 5)) & (tx <= ((int)G.z >> 5)) &
                       (ty >= (((int)G.y - 97) >> 5)) & (ty <= ((int)G.w >> 5));
            if (cov) { if (cnt < CMAX) g_list[t * CMAX + cnt] = (unsigned char)g;
                       ++cnt; }
        }
        g_cnt[t] = cnt;
        __threadfence();
        __syncthreads();
        if (tid == 0) atomicAdd(&g_ready, 1u);
    } else {
        // ---- Consumers: sleep until lists are published.
        if (tid == 0)
            while (atomicAdd(&g_ready, 0u) < NPREP) __nanosleep(64);
        __syncthreads();
        __threadfence();                       // acquire
    }
    __syncthreads();

    // ---- One anchor per thread; branch-free candidate body. Lists/GTs read
    // through L1 (28KB working set, fully resident).
    const int i = b * MT + tid;
    if (i < n) {
        float4 a = __ldg(&anchor[i]);
        float aarea = __fmul_rn(__fsub_rn(a.z, a.x), __fsub_rn(a.w, a.y));
        int t = (((int)a.y >> 5) << 5) + ((int)a.x >> 5);
        int cnt = __ldg(&g_cnt[t]);
        bool hit = false;
        unsigned lowkey = ~(unsigned)i;

        if (cnt <= CMAX) {
            for (int c = 0; c < cnt; ++c) {
                int g = __ldg(&g_list[t * CMAX + c]);
                float4 G = __ldg(&gt[g]);
                float ga = __fmul_rn(__fsub_rn(G.z, G.x), __fsub_rn(G.w, G.y));
                float iw = fmaxf(__fsub_rn(fminf(a.z, G.z), fmaxf(a.x, G.x)), 0.0f);
                float ih = fmaxf(__fsub_rn(fminf(a.w, G.w), fmaxf(a.y, G.y)), 0.0f);
                float inter = __fmul_rn(iw, ih);
                float u = __fsub_rn(__fadd_rn(aarea, ga), inter);
                float q = __fdiv_rn(inter, u);          // == jax fp32 inter/union
                hit |= (q >= 0.3f);
                unsigned long long key =
                    ((unsigned long long)__float_as_uint(q) << 32) | lowkey;
                if (key > s_best[g]) atomicMax(&s_best[g], key);
            }
        } else {                                        // overflow fallback (cold)
            for (int g = 0; g < N_GT; ++g) {
                float4 G = __ldg(&gt[g]);
                float ga = __fmul_rn(__fsub_rn(G.z, G.x), __fsub_rn(G.w, G.y));
                float iw = fmaxf(__fsub_rn(fminf(a.z, G.z), fmaxf(a.x, G.x)), 0.0f);
                float ih = fmaxf(__fsub_rn(fminf(a.w, G.w), fmaxf(a.y, G.y)), 0.0f);
                float inter = __fmul_rn(iw, ih);
                float u = __fsub_rn(__fadd_rn(aarea, ga), inter);
                float q = __fdiv_rn(inter, u);
                hit |= (q >= 0.3f);
                unsigned long long key =
                    ((unsigned long long)__float_as_uint(q) << 32) | lowkey;
                if (key > s_best[g]) atomicMax(&s_best[g], key);
            }
        }
        assign[i] = hit ? -2.0f : -1.0f;    // row result: any exact iou >= 0.3
    }
    __syncthreads();

    // ---- Block -> global column reduction (filtered: read, then atomic).
    if (tid < N_GT) {
        unsigned long long v = s_best[tid];
        if (v) {
            unsigned long long cur = g_best[tid * PAD];
            if (v > cur) atomicMax(&g_best[tid * PAD], v);
        }
    }

    // ---- Last-finishing block claims argmax anchors and resets state.
    __threadfence();
    __syncthreads();
    if (tid == 0) {
        unsigned tkt = atomicAdd(&g_done, 1u);
        s_last = (tkt == GRIDN - 1);
    }
    __syncthreads();
    if (s_last) {
        if (tid < N_GT) {
            unsigned long long v = atomicMax(&g_best[tid * PAD], 0ull); // read
            // v==0: no positive-iou pair -> reference argmax = index 0
            unsigned idx = (v == 0ull) ? 0u
                         : (0xFFFFFFFFu - (unsigned)(v & 0xFFFFFFFFull));
            if (idx < (unsigned)n)
                atomicMax((int*)assign + idx, __float_as_int((float)tid));
            g_best[tid * PAD] = 0ull;       // restore zero-state invariant
        }
        __syncthreads();
        if (tid == 0) { __threadfence(); g_done = 0u; g_ready = 0u; }
    }
}

extern "C" void kernel_launch(void* const* d_in, const int* in_sizes, int n_in,
                              void* d_out, int out_size) {
    int ia = (n_in >= 2 && in_sizes[1] > in_sizes[0]) ? 1 : 0;
    const float4* anchor = (const float4*)d_in[ia];       // [N,4] f32
    const float4* gt     = (const float4*)d_in[1 - ia];   // [128,4] f32
    float* assign = (float*)d_out;                        // float32 output
    int n = in_sizes[ia] / 4;                             // 262144

    fused<<<GRIDN, MT>>>(anchor, gt, assign, n);
    (void)out_size;
}

// round 13
// speedup vs baseline: 1.0770x; 1.0770x over previous
#include <cuda_runtime.h>
#include <cstdint>

#define N_GT    128
#define NTX2    32          // 32x32 tiles of 32px
#define NTILES2 1024
#define MT      256
#define APT     2
#define GRIDN   512         // 512*256*2 = 262144 anchors
#define CMAX    24          // per-tile candidate cap (mean ~4.7, tail ~16)
#define PAD     32          // 256B stride: spreads g_best across LTS slices

__device__ unsigned long long g_best[N_GT * PAD];  // zero-init; reset each run
__device__ unsigned           g_done = 0;          // zero-init; reset each run

__global__ __launch_bounds__(MT, 4) void fused(
    const float4* __restrict__ anchor,
    const float4* __restrict__ gt,
    float* __restrict__ assign, int n)
{
    __shared__ float4 s_g[N_GT];
    __shared__ float  s_ga[N_GT];
    __shared__ unsigned s_rowmask[NTX2][4];      // per tile-row 128-bit GT mask
    __shared__ int    s_txr[N_GT];               // packed txlo | txhi<<8
    __shared__ int    s_cnt[NTILES2];
    __shared__ unsigned char s_list[NTILES2 * CMAX];
    __shared__ unsigned long long s_best[N_GT];
    __shared__ int s_last;

    const int tid = threadIdx.x;
    const int b   = blockIdx.x;

    if (tid < N_GT) {
        float4 g = gt[tid];
        s_g[tid]  = g;
        s_ga[tid] = __fmul_rn(__fsub_rn(g.z, g.x), __fsub_rn(g.w, g.y));
        s_best[tid] = 0ull;
    }
    __syncthreads();

    // ---- Level 1: per tile-row GT masks via ballot + packed x ranges.
    // Tile (tx,ty) must take gt iff an anchor with top-left corner there could
    // overlap it: 32*tx in (G.x-97, G.z)  (conservative integer bounds).
    if (tid < N_GT) {
        float4 G = s_g[tid];
        int txlo = max(0, ((int)G.x - 97) >> 5);
        int txhi = min(NTX2 - 1, (int)G.z >> 5);
        int tylo = max(0, ((int)G.y - 97) >> 5);
        int tyhi = min(NTX2 - 1, (int)G.w >> 5);
        s_txr[tid] = txlo | (txhi << 8);
        int w = tid >> 5;
        #pragma unroll 1
        for (int r = 0; r < NTX2; ++r) {
            unsigned bal = __ballot_sync(0xFFFFFFFFu, (r >= tylo) & (r <= tyhi));
            if ((tid & 31) == 0) s_rowmask[r][w] = bal;
        }
    }
    __syncthreads();

    // ---- Level 2: atomic-free gather, one thread per tile (4 tiles/thread).
    // Lanes in a warp share a tile-row -> uniform masks, uniform trip counts.
    #pragma unroll
    for (int k = 0; k < NTILES2 / MT; ++k) {
        int t   = k * MT + tid;
        int tx  = t & (NTX2 - 1);
        int row = t >> 5;
        int cnt = 0;
        #pragma unroll
        for (int w = 0; w < 4; ++w) {
            unsigned m = s_rowmask[row][w];
            #pragma unroll 1
            while (m) {
                int g = (w << 5) + __ffs(m) - 1;
                m &= m - 1;
                int xr = s_txr[g];
                if ((tx >= (xr & 0xFF)) & (tx <= (xr >> 8))) {
                    if (cnt < CMAX) s_list[t * CMAX + cnt] = (unsigned char)g;
                    ++cnt;
                }
            }
        }
        s_cnt[t] = cnt;
    }
    __syncthreads();

    // ---- IoU phase: APT anchors per thread, branch-free candidate body.
    const int i0 = b * (MT * APT) + tid;
    #pragma unroll
    for (int k = 0; k < APT; ++k) {
        int i = i0 + k * MT;
        float4 a = anchor[i];
        float aarea = __fmul_rn(__fsub_rn(a.z, a.x), __fsub_rn(a.w, a.y));
        int t = (((int)a.y >> 5) << 5) + ((int)a.x >> 5);
        int cnt = s_cnt[t];
        bool hit = false;
        unsigned lowkey = ~(unsigned)i;

        if (cnt <= CMAX) {
            for (int c = 0; c < cnt; ++c) {
                int g = s_list[t * CMAX + c];
                float4 G = s_g[g];
                float iw = fmaxf(__fsub_rn(fminf(a.z, G.z), fmaxf(a.x, G.x)), 0.0f);
                float ih = fmaxf(__fsub_rn(fminf(a.w, G.w), fmaxf(a.y, G.y)), 0.0f);
                float inter = __fmul_rn(iw, ih);
                float u = __fsub_rn(__fadd_rn(aarea, s_ga[g]), inter);
                float q = __fdiv_rn(inter, u);          // == jax fp32 inter/union
                hit |= (q >= 0.3f);
                unsigned long long key =
                    ((unsigned long long)__float_as_uint(q) << 32) | lowkey;
                if (key > s_best[g]) atomicMax(&s_best[g], key);
            }
        } else {                                        // overflow fallback (cold)
            for (int g = 0; g < N_GT; ++g) {
                float4 G = s_g[g];
                float iw = fmaxf(__fsub_rn(fminf(a.z, G.z), fmaxf(a.x, G.x)), 0.0f);
                float ih = fmaxf(__fsub_rn(fminf(a.w, G.w), fmaxf(a.y, G.y)), 0.0f);
                float inter = __fmul_rn(iw, ih);
                float u = __fsub_rn(__fadd_rn(aarea, s_ga[g]), inter);
                float q = __fdiv_rn(inter, u);
                hit |= (q >= 0.3f);
                unsigned long long key =
                    ((unsigned long long)__float_as_uint(q) << 32) | lowkey;
                if (key > s_best[g]) atomicMax(&s_best[g], key);
            }
        }
        assign[i] = hit ? -2.0f : -1.0f;    // row result: any exact iou >= 0.3
    }
    __syncthreads();

    // ---- Block -> global column reduction (filtered: read, then atomic).
    if (tid < N_GT) {
        unsigned long long v = s_best[tid];
        if (v) {
            unsigned long long cur = g_best[tid * PAD];
            if (v > cur) atomicMax(&g_best[tid * PAD], v);
        }
    }

    // ---- Last-finishing block claims argmax anchors and resets state.
    __threadfence();
    __syncthreads();
    if (tid == 0) {
        unsigned tkt = atomicAdd(&g_done, 1u);
        s_last = (tkt == GRIDN - 1);
    }
    __syncthreads();
    if (s_last) {
        if (tid < N_GT) {
            unsigned long long v = atomicMax(&g_best[tid * PAD], 0ull); // read
            // v==0: no positive-iou pair -> reference argmax = index 0
            unsigned idx = (v == 0ull) ? 0u
                         : (0xFFFFFFFFu - (unsigned)(v & 0xFFFFFFFFull));
            if (idx < (unsigned)n)
                atomicMax((int*)assign + idx, __float_as_int((float)tid));
            g_best[tid * PAD] = 0ull;       // restore zero-state invariant
        }
        __syncthreads();
        if (tid == 0) { __threadfence(); g_done = 0u; }
    }
}

extern "C" void kernel_launch(void* const* d_in, const int* in_sizes, int n_in,
                              void* d_out, int out_size) {
    int ia = (n_in >= 2 && in_sizes[1] > in_sizes[0]) ? 1 : 0;
    const float4* anchor = (const float4*)d_in[ia];       // [N,4] f32
    const float4* gt     = (const float4*)d_in[1 - ia];   // [128,4] f32
    float* assign = (float*)d_out;                        // float32 output
    int n = in_sizes[ia] / 4;                             // 262144

    fused<<<GRIDN, MT>>>(anchor, gt, assign, n);
    (void)out_size;
}

// round 14
// speedup vs baseline: 1.4836x; 1.3775x over previous
#include <cuda_runtime.h>
#include <cstdint>

#define N_GT   128
#define NTX2   32          // 32x32 tiles of 32px
#define MT     256
#define GRIDN  1024        // 1 anchor per thread
#define PAD    32          // 256B stride: spreads g_best across LTS slices

__device__ unsigned long long g_best[N_GT * PAD];  // zero-init; reset each run
__device__ unsigned           g_done = 0;          // zero-init; reset each run

__global__ __launch_bounds__(MT) void fused(
    const float4* __restrict__ anchor,
    const float4* __restrict__ gt,
    float* __restrict__ assign, int n)
{
    __shared__ float4 s_g[N_GT];
    __shared__ float  s_ga[N_GT];
    __shared__ uint4  s_row[NTX2];     // 128-bit GT mask per tile-row
    __shared__ uint4  s_col[NTX2];     // 128-bit GT mask per tile-col
    __shared__ unsigned long long s_best[N_GT];
    __shared__ int s_last;

    const int tid = threadIdx.x;
    const int b   = blockIdx.x;

    if (tid < N_GT) {
        float4 g = gt[tid];
        s_g[tid]  = g;
        s_ga[tid] = __fmul_rn(__fsub_rn(g.z, g.x), __fsub_rn(g.w, g.y));
        s_best[tid] = 0ull;
    }
    __syncthreads();

    // ---- Setup: separable coverage masks via ballot (64 ballots total).
    // GT covers tile (tx,ty) iff tx in [txlo,txhi] AND ty in [tylo,tyhi]
    // (conservative: anchor top-left in tile, anchor extent <= 65, tile 32).
    if (tid < N_GT) {
        float4 G = s_g[tid];
        int txlo = max(0, ((int)G.x - 97) >> 5);
        int txhi = min(NTX2 - 1, (int)G.z >> 5);
        int tylo = max(0, ((int)G.y - 97) >> 5);
        int tyhi = min(NTX2 - 1, (int)G.w >> 5);
        int w = tid >> 5, l = tid & 31;
        #pragma unroll 1
        for (int r = 0; r < NTX2; ++r) {
            unsigned br = __ballot_sync(0xFFFFFFFFu, (r >= tylo) & (r <= tyhi));
            unsigned bc = __ballot_sync(0xFFFFFFFFu, (r >= txlo) & (r <= txhi));
            if (l == 0) {
                ((unsigned*)&s_row[r])[w] = br;
                ((unsigned*)&s_col[r])[w] = bc;
            }
        }
    }
    __syncthreads();

    // ---- One anchor per thread: AND masks, bit-walk true candidates only.
    const int i = b * MT + tid;
    if (i < n) {
        float4 a = anchor[i];
        float aarea = __fmul_rn(__fsub_rn(a.z, a.x), __fsub_rn(a.w, a.y));
        int tx = min(NTX2 - 1, (int)a.x >> 5);
        int ty = min(NTX2 - 1, (int)a.y >> 5);
        uint4 rm = s_row[ty];
        uint4 cm = s_col[tx];
        unsigned long long m[2] = {
            (unsigned long long)(rm.x & cm.x) |
            ((unsigned long long)(rm.y & cm.y) << 32),
            (unsigned long long)(rm.z & cm.z) |
            ((unsigned long long)(rm.w & cm.w) << 32) };
        bool hit = false;
        unsigned lowkey = ~(unsigned)i;

        #pragma unroll
        for (int hw = 0; hw < 2; ++hw) {
            unsigned long long mm = m[hw];
            int gbase = hw << 6;
            #pragma unroll 1
            while (mm) {
                int g = gbase + __ffsll(mm) - 1;
                mm &= mm - 1;
                float4 G = s_g[g];
                float iw = fmaxf(__fsub_rn(fminf(a.z, G.z), fmaxf(a.x, G.x)), 0.0f);
                float ih = fmaxf(__fsub_rn(fminf(a.w, G.w), fmaxf(a.y, G.y)), 0.0f);
                float inter = __fmul_rn(iw, ih);
                float u = __fsub_rn(__fadd_rn(aarea, s_ga[g]), inter);
                float q = __fdiv_rn(inter, u);          // == jax fp32 inter/union
                hit |= (q >= 0.3f);
                unsigned long long key =
                    ((unsigned long long)__float_as_uint(q) << 32) | lowkey;
                if (key > s_best[g]) atomicMax(&s_best[g], key);
            }
        }
        assign[i] = hit ? -2.0f : -1.0f;    // row result: any exact iou >= 0.3
    }
    __syncthreads();

    // ---- Block -> global column reduction (filtered: read, then atomic).
    if (tid < N_GT) {
        unsigned long long v = s_best[tid];
        if (v) {
            unsigned long long cur = g_best[tid * PAD];
            if (v > cur) atomicMax(&g_best[tid * PAD], v);
        }
    }

    // ---- Last-finishing block claims argmax anchors and resets state.
    __threadfence();
    __syncthreads();
    if (tid == 0) {
        unsigned tkt = atomicAdd(&g_done, 1u);
        s_last = (tkt == GRIDN - 1);
    }
    __syncthreads();
    if (s_last) {
        if (tid < N_GT) {
            unsigned long long v = atomicMax(&g_best[tid * PAD], 0ull); // read
            // v==0: no positive-iou pair -> reference argmax = index 0
            unsigned idx = (v == 0ull) ? 0u
                         : (0xFFFFFFFFu - (unsigned)(v & 0xFFFFFFFFull));
            if (idx < (unsigned)n)
                atomicMax((int*)assign + idx, __float_as_int((float)tid));
            g_best[tid * PAD] = 0ull;       // restore zero-state invariant
        }
        __syncthreads();
        if (tid == 0) { __threadfence(); g_done = 0u; }
    }
}

extern "C" void kernel_launch(void* const* d_in, const int* in_sizes, int n_in,
                              void* d_out, int out_size) {
    int ia = (n_in >= 2 && in_sizes[1] > in_sizes[0]) ? 1 : 0;
    const float4* anchor = (const float4*)d_in[ia];       // [N,4] f32
    const float4* gt     = (const float4*)d_in[1 - ia];   // [128,4] f32
    float* assign = (float*)d_out;                        // float32 output
    int n = in_sizes[ia] / 4;                             // 262144

    fused<<<GRIDN, MT>>>(anchor, gt, assign, n);
    (void)out_size;
}

// round 16
// speedup vs baseline: 1.6162x; 1.0894x over previous
#include <cuda_runtime.h>
#include <cstdint>

#define N_GT   128
#define NTX    64          // 64x64 tiles of 16px
#define MT     256
#define GRIDN  1024        // 1 anchor per thread
#define QCAP   192         // per-warp queue capacity (mean ~104, 8.6 sigma)
#define PAD    32          // 256B stride: spreads g_best across LTS slices
#define FULLM  0xFFFFFFFFu

__device__ unsigned long long g_best[N_GT * PAD];  // zero-init; reset each run
__device__ unsigned           g_done = 0;          // zero-init; reset each run

__global__ __launch_bounds__(MT) void fused(
    const float4* __restrict__ anchor,
    const float4* __restrict__ gt,
    float* __restrict__ assign, int n)
{
    __shared__ float4 s_g[N_GT];
    __shared__ float  s_ga[N_GT];
    __shared__ uint4  s_row[NTX];      // 128-bit GT mask per tile-row
    __shared__ uint4  s_col[NTX];      // 128-bit GT mask per tile-col
    __shared__ unsigned long long s_best[N_GT];
    __shared__ unsigned short s_q[MT / 32][QCAP];
    __shared__ int s_last;

    const int tid  = threadIdx.x;
    const int b    = blockIdx.x;
    const int lane = tid & 31;
    const int wid  = tid >> 5;

    if (tid < N_GT) {
        float4 g = gt[tid];
        s_g[tid]  = g;
        s_ga[tid] = __fmul_rn(__fsub_rn(g.z, g.x), __fsub_rn(g.w, g.y));
        s_best[tid] = 0ull;
    }
    __syncthreads();

    // ---- Separable coverage masks via ballot. GT covers tile t iff an anchor
    // with top-left corner in t could overlap it (extent <= 65, tile 16 -> 81).
    if (tid < N_GT) {
        float4 G = s_g[tid];
        int txlo = max(0, ((int)G.x - 81) >> 4);
        int txhi = min(NTX - 1, (int)G.z >> 4);
        int tylo = max(0, ((int)G.y - 81) >> 4);
        int tyhi = min(NTX - 1, (int)G.w >> 4);
        int w = tid >> 5;
        #pragma unroll 1
        for (int r = 0; r < NTX; ++r) {
            unsigned br = __ballot_sync(FULLM, (r >= tylo) & (r <= tyhi));
            unsigned bc = __ballot_sync(FULLM, (r >= txlo) & (r <= txhi));
            if (lane == 0) {
                ((unsigned*)&s_row[r])[w] = br;
                ((unsigned*)&s_col[r])[w] = bc;
            }
        }
    }
    __syncthreads();

    // ---- Per-anchor candidate mask, then warp-compacted dense processing.
    const int i = b * MT + tid;
    float4 a = anchor[i];
    float aarea = __fmul_rn(__fsub_rn(a.z, a.x), __fsub_rn(a.w, a.y));
    int tx = min(NTX - 1, (int)a.x >> 4);
    int ty = min(NTX - 1, (int)a.y >> 4);
    uint4 rm = s_row[ty];
    uint4 cm = s_col[tx];
    unsigned long long m0 = (unsigned long long)(rm.x & cm.x) |
                            ((unsigned long long)(rm.y & cm.y) << 32);
    unsigned long long m1 = (unsigned long long)(rm.z & cm.z) |
                            ((unsigned long long)(rm.w & cm.w) << 32);

    int pc = __popcll(m0) + __popcll(m1);
    int incl = pc;
    #pragma unroll
    for (int o = 1; o < 32; o <<= 1) {
        int v = __shfl_up_sync(FULLM, incl, o);
        if (lane >= o) incl += v;
    }
    int off  = incl - pc;
    int ntot = __shfl_sync(FULLM, incl, 31);

    // Drain own mask bits into the warp queue (divergent but cheap body).
    unsigned short tag = (unsigned short)(lane << 8);
    #pragma unroll 1
    while (m0 && off < QCAP) {
        int g = __ffsll(m0) - 1; m0 &= m0 - 1;
        s_q[wid][off++] = (unsigned short)g | tag;
    }
    #pragma unroll 1
    while (m1 && off < QCAP) {
        int g = 64 + __ffsll(m1) - 1; m1 &= m1 - 1;
        s_q[wid][off++] = (unsigned short)g | tag;
    }
    __syncwarp();

    // Dense converged trips over the queue; anchor data via shfl from owner.
    bool myhit = false;
    int nt = min(ntot, QCAP);
    int trips = (nt + 31) >> 5;
    const int warpbase = b * MT + (wid << 5);
    #pragma unroll 1
    for (int t = 0; t < trips; ++t) {
        int qi = (t << 5) + lane;
        bool valid = qi < nt;
        unsigned e = valid ? s_q[wid][qi] : 0u;
        int g     = e & 255;
        int owner = e >> 8;
        float ax = __shfl_sync(FULLM, a.x, owner);
        float ay = __shfl_sync(FULLM, a.y, owner);
        float az = __shfl_sync(FULLM, a.z, owner);
        float aw = __shfl_sync(FULLM, a.w, owner);
        float oarea = __shfl_sync(FULLM, aarea, owner);
        float4 G = s_g[g];
        float iw = fmaxf(__fsub_rn(fminf(az, G.z), fmaxf(ax, G.x)), 0.0f);
        float ih = fmaxf(__fsub_rn(fminf(aw, G.w), fmaxf(ay, G.y)), 0.0f);
        float inter = __fmul_rn(iw, ih);
        float u = __fsub_rn(__fadd_rn(oarea, s_ga[g]), inter);
        float q = __fdiv_rn(inter, u);              // == jax fp32 inter/union
        bool ov = valid && (inter > 0.0f);
        bool hc = ov && (q >= 0.3f);
        unsigned hb = __reduce_or_sync(FULLM, hc ? (1u << owner) : 0u);
        myhit |= (hb >> lane) & 1u;
        if (ov) {
            unsigned qb = __float_as_uint(q);
            unsigned hi = ((unsigned*)&s_best[g])[1];   // monotone filter read
            if (qb >= hi) {
                unsigned long long key = ((unsigned long long)qb << 32) |
                    (unsigned)(0xFFFFFFFFu - (unsigned)(warpbase + owner));
                atomicMax(&s_best[g], key);
            }
        }
    }

    // Overflow leftover (p ~ 1e-8): divergent walk on remaining bits.
    if (m0 | m1) {
        unsigned lowkey = 0xFFFFFFFFu - (unsigned)i;
        #pragma unroll 1
        for (int hw = 0; hw < 2; ++hw) {
            unsigned long long mm = hw ? m1 : m0;
            int gb = hw << 6;
            while (mm) {
                int g = gb + __ffsll(mm) - 1; mm &= mm - 1;
                float4 G = s_g[g];
                float iw = fmaxf(__fsub_rn(fminf(a.z, G.z), fmaxf(a.x, G.x)), 0.0f);
                float ih = fmaxf(__fsub_rn(fminf(a.w, G.w), fmaxf(a.y, G.y)), 0.0f);
                float inter = __fmul_rn(iw, ih);
                float u = __fsub_rn(__fadd_rn(aarea, s_ga[g]), inter);
                float q = __fdiv_rn(inter, u);
                if (inter > 0.0f) {
                    myhit |= (q >= 0.3f);
                    unsigned long long key =
                        ((unsigned long long)__float_as_uint(q) << 32) | lowkey;
                    if (key > s_best[g]) atomicMax(&s_best[g], key);
                }
            }
        }
    }

    assign[i] = myhit ? -2.0f : -1.0f;     // row result: any exact iou >= 0.3
    __syncthreads();

    // ---- Block -> global column reduction (filtered: read, then atomic).
    if (tid < N_GT) {
        unsigned long long v = s_best[tid];
        if (v) {
            unsigned long long cur = g_best[tid * PAD];
            if (v > cur) atomicMax(&g_best[tid * PAD], v);
        }
    }

    // ---- Last-finishing block claims argmax anchors and resets state.
    __threadfence();
    __syncthreads();
    if (tid == 0) {
        unsigned tkt = atomicAdd(&g_done, 1u);
        s_last = (tkt == GRIDN - 1);
    }
    __syncthreads();
    if (s_last) {
        if (tid < N_GT) {
            unsigned long long v = atomicMax(&g_best[tid * PAD], 0ull); // read
            // v==0: no positive-iou pair -> reference argmax = index 0
            unsigned idx = (v == 0ull) ? 0u
                         : (0xFFFFFFFFu - (unsigned)(v & 0xFFFFFFFFull));
            if (idx < (unsigned)n)
                atomicMax((int*)assign + idx, __float_as_int((float)tid));
            g_best[tid * PAD] = 0ull;       // restore zero-state invariant
        }
        __syncthreads();
        if (tid == 0) { __threadfence(); g_done = 0u; }
    }
}

extern "C" void kernel_launch(void* const* d_in, const int* in_sizes, int n_in,
                              void* d_out, int out_size) {
    int ia = (n_in >= 2 && in_sizes[1] > in_sizes[0]) ? 1 : 0;
    const float4* anchor = (const float4*)d_in[ia];       // [N,4] f32
    const float4* gt     = (const float4*)d_in[1 - ia];   // [128,4] f32
    float* assign = (float*)d_out;                        // float32 output
    int n = in_sizes[ia] / 4;                             // 262144

    fused<<<GRIDN, MT>>>(anchor, gt, assign, n);
    (void)out_size;
}